// round 17
// baseline (speedup 1.0000x reference)
#include <cuda_runtime.h>
#include <cstdint>

#define SIZE_SETS 50000
#define NS 32
#define OUTP 64
#define NROWS (SIZE_SETS * NS)
#define WPB 4
#define BN_BLOCKS 592

// ---------------- device scratch (no allocation allowed) ----------------
// g_acc layout per set: 4 quads [4*t + {e_{2t}, e_{2t+1}, ve_{2t}, ve_{2t+1}}], t=0..3
__device__ __align__(128) float g_acc[SIZE_SETS * 16];
__device__ float g_bnp[BN_BLOCKS][5];
__device__ float g_consts[32];   // [0..3]=A, [4..5]=shift, [6..13]=C0, [14..21]=C1, [22..29]=D

// ---------------- helpers ----------------
__device__ __forceinline__ void fadd2(unsigned long long& d, unsigned long long a) {
    asm("add.rn.f32x2 %0, %1, %0;" : "+l"(d) : "l"(a));
}
__device__ __forceinline__ float2 unpk(unsigned long long v) {
    float2 r; asm("mov.b64 {%0, %1}, %2;" : "=f"(r.x), "=f"(r.y) : "l"(v)); return r;
}
__device__ __forceinline__ unsigned long long pk(float x, float y) {
    unsigned long long r; asm("mov.b64 %0, {%1, %2};" : "=l"(r) : "f"(x), "f"(y)); return r;
}
__device__ __forceinline__ void red4(float* p, float a, float b, float c, float d) {
    asm volatile("red.global.add.v4.f32 [%0], {%1, %2, %3, %4};"
                 :: "l"(p), "f"(a), "f"(b), "f"(c), "f"(d) : "memory");
}
__device__ __forceinline__ uint32_t prmt(uint32_t a, uint32_t b, uint32_t s) {
    uint32_t d; asm("prmt.b32 %0, %1, %2, %3;" : "=r"(d) : "r"(a), "r"(b), "r"(s)); return d;
}
__device__ __forceinline__ uint32_t cvtbf2(float x1, float x0) {
    uint32_t d; asm("cvt.rn.bf16x2.f32 %0, %1, %2;" : "=r"(d) : "f"(x1), "f"(x0)); return d;
}
// hi/lo split of an f32 pair into two bf16x2 regs (hi = truncation, exact in bf16)
__device__ __forceinline__ void split2(float x0, float x1, uint32_t& hi, uint32_t& lo) {
    uint32_t u0 = __float_as_uint(x0), u1 = __float_as_uint(x1);
    hi = prmt(u0, u1, 0x7632);
    float l0 = x0 - __uint_as_float(u0 & 0xffff0000u);
    float l1 = x1 - __uint_as_float(u1 & 0xffff0000u);
    lo = cvtbf2(l1, l0);
}
__device__ __forceinline__ void mma16816(float* c, const uint32_t* a, const uint32_t* b) {
    asm("mma.sync.aligned.m16n8k16.row.col.f32.bf16.bf16.f32 "
        "{%0,%1,%2,%3}, {%4,%5,%6,%7}, {%8,%9}, {%0,%1,%2,%3};"
        : "+f"(c[0]), "+f"(c[1]), "+f"(c[2]), "+f"(c[3])
        : "r"(a[0]), "r"(a[1]), "r"(a[2]), "r"(a[3]), "r"(b[0]), "r"(b[1]));
}

// ---------------- kernel 1: zero g_acc + per-block raw moments of translation ----------------
__global__ void k_bn(const float* __restrict__ tr) {
    for (int k = blockIdx.x * blockDim.x + threadIdx.x; k < SIZE_SETS * 16;
         k += gridDim.x * blockDim.x) g_acc[k] = 0.f;

    float s0 = 0.f, s1 = 0.f, q00 = 0.f, q01 = 0.f, q11 = 0.f;
    const float2* t2 = (const float2*)tr;
    for (int i = blockIdx.x * blockDim.x + threadIdx.x; i < NROWS; i += gridDim.x * blockDim.x) {
        float2 t = t2[i];
        s0 += t.x; s1 += t.y;
        q00 += t.x * t.x; q01 += t.x * t.y; q11 += t.y * t.y;
    }
    #pragma unroll
    for (int o = 16; o; o >>= 1) {
        s0  += __shfl_down_sync(0xffffffffu, s0, o);
        s1  += __shfl_down_sync(0xffffffffu, s1, o);
        q00 += __shfl_down_sync(0xffffffffu, q00, o);
        q01 += __shfl_down_sync(0xffffffffu, q01, o);
        q11 += __shfl_down_sync(0xffffffffu, q11, o);
    }
    __shared__ float sh[5][8];
    int w = threadIdx.x >> 5, l = threadIdx.x & 31;
    if (l == 0) { sh[0][w] = s0; sh[1][w] = s1; sh[2][w] = q00; sh[3][w] = q01; sh[4][w] = q11; }
    __syncthreads();
    if (threadIdx.x < 5) {
        float t = 0.f;
        #pragma unroll
        for (int k = 0; k < 8; k++) t += sh[threadIdx.x][k];
        g_bnp[blockIdx.x][threadIdx.x] = t;
    }
}

// ---------------- kernel 2: reduce moments, fold BN + positional constants ----------------
__global__ void k_setup(const float* __restrict__ Wq, const float* __restrict__ bq,
                        const float* __restrict__ Wp1, const float* __restrict__ gamma,
                        const float* __restrict__ beta, const float* __restrict__ Wp2,
                        const float* __restrict__ bp2) {
    __shared__ double bn[5];
    int t = threadIdx.x;
    if (t < 5) {
        double acc = 0.0;
        for (int i = 0; i < BN_BLOCKS; i++) acc += (double)g_bnp[i][t];
        bn[t] = acc;
    }
    __syncthreads();
    if (t < 2) {
        double Nf = (double)NROWS;
        double w0 = (double)Wp1[t * 2 + 0], w1 = (double)Wp1[t * 2 + 1];
        double Tsum = w0 * bn[0] + w1 * bn[1];
        double Tsq  = w0 * w0 * bn[2] + 2.0 * w0 * w1 * bn[3] + w1 * w1 * bn[4];
        double mean = Tsum / Nf;
        double var  = Tsq / Nf - mean * mean;
        double scale = (double)gamma[t] / sqrt(var + 1e-5);
        double shift = (double)beta[t] - mean * scale;
        g_consts[t * 2 + 0] = (float)(w0 * scale);
        g_consts[t * 2 + 1] = (float)(w1 * scale);
        g_consts[4 + t]     = (float)shift;
    }
    if (t < 8) {
        float c0 = 0.f, c1 = 0.f, d = 0.f;
        for (int k = 0; k < OUTP; k++) {
            float wq = Wq[t * OUTP + k];
            c0 += Wp2[k * 2 + 0] * wq;
            c1 += Wp2[k * 2 + 1] * wq;
            d  += bp2[k] * wq;
        }
        g_consts[6 + t]  = c0;
        g_consts[14 + t] = c1;
        g_consts[22 + t] = d + bq[t];
    }
}

// ---------------- kernel 3: fused main — warp = set, direct-LDG A-frags, no staging ----------------
__global__ void __launch_bounds__(128)
k_main(const float* __restrict__ outputs, const float* __restrict__ translation,
       const int* __restrict__ indexes, const float* __restrict__ Wq,
       const float* __restrict__ Wv, const float* __restrict__ bv_,
       float* __restrict__ out) {
    __shared__ __align__(8) float2 sh_a[WPB][32];
    __shared__ int sh_idx[WPB][32];

    int tid = threadIdx.x, warp = tid >> 5, lane = tid & 31;
    int g = lane >> 2, t4 = lane & 3;
    int j0 = 2 * t4, j1 = 2 * t4 + 1;

    const float A00 = g_consts[0], A01 = g_consts[1], A10 = g_consts[2], A11 = g_consts[3];
    const float SH0 = g_consts[4], SH1 = g_consts[5];
    const float C0a = g_consts[6 + j0],  C0b = g_consts[6 + j1];
    const float C1a = g_consts[14 + j0], C1b = g_consts[14 + j1];
    const float Da  = g_consts[22 + j0], Db  = g_consts[22 + j1];
    const float bva = bv_[j0], bvb = bv_[j1];

    // --- weight B-fragments in registers, hi/lo bf16 split (loaded once) ---
    uint32_t bqh[4][2], bql[4][2], bvh[4][2], bvl[4][2];
    #pragma unroll
    for (int kt = 0; kt < 4; kt++)
        #pragma unroll
        for (int r = 0; r < 2; r++) {
            int k = kt * 16 + 2 * t4 + 8 * r;
            split2(Wq[g * 64 + k], Wq[g * 64 + k + 1], bqh[kt][r], bql[kt][r]);
            split2(Wv[g * 64 + k], Wv[g * 64 + k + 1], bvh[kt][r], bvl[kt][r]);
        }

    // per-lane A-frag base offset within a set: row g, col 2*t4
    const int lane_off = g * OUTP + 2 * t4;
    // feature write column for this lane's pair #g
    const int colp = 2 * t4 + 8 * (g & 1) + 16 * (g >> 1);

    for (int s = blockIdx.x * WPB + warp; s < SIZE_SETS; s += gridDim.x * WPB) {
        // --- per-row metadata (lane = row) ---
        float2 tv = ((const float2*)translation)[s * NS + lane];
        sh_idx[warp][lane] = indexes[s * NS + lane];
        sh_a[warp][lane] = make_float2(
            fmaxf(fmaf(A00, tv.x, fmaf(A01, tv.y, SH0)), 0.f),
            fmaxf(fmaf(A10, tv.x, fmaf(A11, tv.y, SH1)), 0.f));
        __syncwarp();

        const float* xs = outputs + (size_t)s * (NS * OUTP) + lane_off;

        float cq[2][4], cv[2][4];
        #pragma unroll
        for (int mt = 0; mt < 2; mt++)
            #pragma unroll
            for (int i = 0; i < 4; i++) { cq[mt][i] = 0.f; cv[mt][i] = 0.f; }

        unsigned long long fs[8];   // feature partials: [kt*2+b], rows {g,g+8,g+16,g+24}
        #pragma unroll
        for (int p = 0; p < 8; p++) fs[p] = 0ull;

        #pragma unroll
        for (int kt = 0; kt < 4; kt++) {
            // batch all 8 A-frag LDG.64 for this ktile (sector-perfect: 8 rows x 32B)
            float2 xv[2][4];
            #pragma unroll
            for (int mt = 0; mt < 2; mt++)
                #pragma unroll
                for (int rr = 0; rr < 4; rr++)
                    xv[mt][rr] = *(const float2*)(xs + ((rr & 1) * 8 + mt * 16) * OUTP
                                                     + (rr >> 1) * 8 + kt * 16);
            // feature accumulation (free: data already in regs)
            #pragma unroll
            for (int mt = 0; mt < 2; mt++)
                #pragma unroll
                for (int rr = 0; rr < 4; rr++)
                    fadd2(fs[kt * 2 + (rr >> 1)], pk(xv[mt][rr].x, xv[mt][rr].y));
            // 3-pass bf16-split MMAs
            #pragma unroll
            for (int mt = 0; mt < 2; mt++) {
                uint32_t ah[4], al[4];
                #pragma unroll
                for (int rr = 0; rr < 4; rr++)
                    split2(xv[mt][rr].x, xv[mt][rr].y, ah[rr], al[rr]);
                mma16816(cq[mt], ah, bqh[kt]);
                mma16816(cq[mt], al, bqh[kt]);
                mma16816(cq[mt], ah, bql[kt]);
                mma16816(cv[mt], ah, bvh[kt]);
                mma16816(cv[mt], al, bvh[kt]);
                mma16816(cv[mt], ah, bvl[kt]);
            }
        }

        // --- complete feature column sums: butterfly over g bits (lanes 4 apart) ---
        #pragma unroll
        for (int m = 4; m <= 16; m <<= 1)
            #pragma unroll
            for (int p = 0; p < 8; p++)
                fadd2(fs[p], __shfl_xor_sync(0xffffffffu, fs[p], m));
        // lane (g,t4) writes pair #g -> one fully coalesced 256B STG.64 per set
        {
            unsigned long long mine = fs[0];
            #pragma unroll
            for (int p = 1; p < 8; p++) if (g == p) mine = fs[p];
            float2 f = unpk(mine);
            *(float2*)&out[(size_t)s * OUTP + colp] = f;
        }

        // --- epilogue: C-frag (rows g+8a+16mt, cols 2t4,2t4+1) -> exp -> red.v4 ---
        #pragma unroll
        for (int mt = 0; mt < 2; mt++)
            #pragma unroll
            for (int aa = 0; aa < 2; aa++) {
                int r = g + 8 * aa + 16 * mt;
                float2 arow = sh_a[warp][r];
                int idx = sh_idx[warp][r];
                float q0 = cq[mt][2 * aa + 0] + fmaf(arow.x, C0a, fmaf(arow.y, C1a, Da));
                float q1 = cq[mt][2 * aa + 1] + fmaf(arow.x, C0b, fmaf(arow.y, C1b, Db));
                float e0 = __expf(q0), e1 = __expf(q1);   // max-shift removed (q bounded)
                float ve0 = (cv[mt][2 * aa + 0] + bva) * e0;
                float ve1 = (cv[mt][2 * aa + 1] + bvb) * e1;
                red4(&g_acc[(size_t)idx * 16 + 4 * t4], e0, e1, ve0, ve1);
            }
        __syncwarp();
    }
}

// ---------------- kernel 4: finalize out += tiled(numer/gsum) ----------------
__global__ void k_fin(float* __restrict__ out) {
    int i = blockIdx.x * blockDim.x + threadIdx.x;      // float4 index into out
    if (i < SIZE_SETS * 16) {
        int s  = i >> 4;
        int c4 = i & 15;
        const float4* acc4 = (const float4*)g_acc;
        float4 P0 = acc4[s * 4 + (c4 & 1) * 2 + 0];     // {e_j, e_j+1, ve_j, ve_j+1}
        float4 P1 = acc4[s * 4 + (c4 & 1) * 2 + 1];
        float4 o = *(float4*)&out[(size_t)i * 4];
        o.x += (P0.x > 0.f) ? P0.z / P0.x : 0.f;
        o.y += (P0.y > 0.f) ? P0.w / P0.y : 0.f;
        o.z += (P1.x > 0.f) ? P1.z / P1.x : 0.f;
        o.w += (P1.y > 0.f) ? P1.w / P1.y : 0.f;
        *(float4*)&out[(size_t)i * 4] = o;
    }
}

// ---------------- launch ----------------
extern "C" void kernel_launch(void* const* d_in, const int* in_sizes, int n_in,
                              void* d_out, int out_size) {
    const float* outputs     = (const float*)d_in[0];
    const float* translation = (const float*)d_in[1];
    const int*   indexes     = (const int*)d_in[2];
    const float* W_q   = (const float*)d_in[3];
    const float* b_q   = (const float*)d_in[4];
    const float* W_v   = (const float*)d_in[5];
    const float* b_v   = (const float*)d_in[6];
    const float* W_p1  = (const float*)d_in[7];
    const float* gamma = (const float*)d_in[8];
    const float* beta  = (const float*)d_in[9];
    const float* W_p2  = (const float*)d_in[10];
    const float* b_p2  = (const float*)d_in[11];
    float* out = (float*)d_out;

    k_bn<<<BN_BLOCKS, 256>>>(translation);
    k_setup<<<1, 64>>>(W_q, b_q, W_p1, gamma, beta, W_p2, b_p2);
    k_main<<<1184, 128>>>(outputs, translation, indexes, W_q, W_v, b_v, out);
    k_fin<<<(SIZE_SETS * 16 + 255) / 256, 256>>>(out);
}